// round 3
// baseline (speedup 1.0000x reference)
#include <cuda_runtime.h>
#include <math.h>
#include <stdint.h>

#define B_AG 32768
#define DID  512
#define HID  1024
#define NOPT 8
#define NACT 16

#define TB 64
#define TN 128
#define KC 32
#define NT 256
#define NCHUNK (DID/KC)   // 16

#define OS   36           // obs smem row stride (floats): delta 36 % 32 = 4 -> conflict-free
#define WTS  34           // transposed-weight smem col stride: tx*34 % 32 = 2tx -> conflict-free
#define HSS  132          // hidden staging stride
#define HWS  20           // head-weight stride

#define OBS_BUF_F (TB*OS)             // 2304
#define WS_BUF_F  (TN*WTS)            // 4352
#define OBS_OFF 0
#define WS_OFF   (2*OBS_BUF_F)        // 4608
#define HW_OFF   (WS_OFF + 2*WS_BUF_F)   // 13312
#define BIAS_OFF (HW_OFF + TN*HWS)       // 15872
#define FIN_OFF  (BIAS_OFF + TN)         // 16000
#define MISC_OFF (FIN_OFF + TB*HWS)      // 17280
#define SMEM_FLOATS (MISC_OFF + 96)      // 17376
#define SMEM_BYTES  (SMEM_FLOATS*4)      // 69504

typedef unsigned long long ull;

__device__ int   g_opt_cnt[NOPT];
__device__ int   g_opt_list[NOPT*B_AG];
__device__ float g_wT[10*HID*DID];   // K-major weights: [mat][h][k]

// ---------------------------------------------------------------------------
// One-time per launch: transpose the 10 big weight matrices to K-major, and
// reset the option counters (runs before meta kernel on the same stream).
// ---------------------------------------------------------------------------
__global__ void __launch_bounds__(256)
transpose_kernel(const float* __restrict__ Wm1,
                 const float* __restrict__ Wt1,
                 const float* __restrict__ W1)
{
    __shared__ float tile[32][33];
    const int m = blockIdx.z;
    const float* src = (m == 0) ? Wm1 : (m == 1) ? Wt1
                                      : W1 + (size_t)(m-2)*DID*HID;
    float* dst = g_wT + (size_t)m*HID*DID;
    const int h0 = blockIdx.x * 32;
    const int k0 = blockIdx.y * 32;
    const int tx = threadIdx.x, ty0 = threadIdx.y;

    #pragma unroll
    for (int r = 0; r < 32; r += 8)
        tile[r + ty0][tx] = src[(size_t)(k0 + r + ty0)*HID + h0 + tx];
    __syncthreads();
    #pragma unroll
    for (int r = 0; r < 32; r += 8)
        dst[(size_t)(h0 + r + ty0)*DID + k0 + tx] = tile[tx][r + ty0];

    if (m == 0 && blockIdx.x == 0 && blockIdx.y == 0 && ty0 == 0 && tx < NOPT)
        g_opt_cnt[tx] = 0;
}

// ---------------------------------------------------------------------------
// helpers
// ---------------------------------------------------------------------------
__device__ __forceinline__ float2 unpack2(ull v) {
    float2 f;
    asm("mov.b64 {%0, %1}, %2;" : "=f"(f.x), "=f"(f.y) : "l"(v));
    return f;
}
__device__ __forceinline__ void fma2(ull& d, ull a, ull b) {
    asm("fma.rn.f32x2 %0, %1, %2, %3;" : "=l"(d) : "l"(a), "l"(b), "l"(d));
}
__device__ __forceinline__ void cp16(uint32_t dst, const float* src) {
    asm volatile("cp.async.cg.shared.global [%0], [%1], 16;" :: "r"(dst), "l"(src));
}
__device__ __forceinline__ void cp8(uint32_t dst, const float* src) {
    asm volatile("cp.async.ca.shared.global [%0], [%1], 8;" :: "r"(dst), "l"(src));
}
#define CP_COMMIT() asm volatile("cp.async.commit_group;")
#define CP_WAIT1()  asm volatile("cp.async.wait_group 1;")
#define CP_WAIT0()  asm volatile("cp.async.wait_group 0;")

// ---------------------------------------------------------------------------
// Core: one [64 x 128] hidden tile, K=512, K-pair FFMA2, double-buffered.
// acc[i][j]: f32x2 (even-k partial, odd-k partial) for row ty+16i, col tx+16j.
// obs_src: per-thread gmem base (row t>>2, float offset (t&3)*8).
// w_src:   per-thread gmem base in K-major weights (col t>>1, k offset (t&1)*16).
// Ends with all threads synced.
// ---------------------------------------------------------------------------
__device__ __forceinline__ void gemm_htile(float* __restrict__ sm,
    const float* __restrict__ obs_src, const float* __restrict__ w_src,
    int t, ull acc[4][8])
{
    const int tx = t & 15, ty = t >> 4;
    const uint32_t su   = (uint32_t)__cvta_generic_to_shared(sm);
    const uint32_t o_d  = su + (uint32_t)((OBS_OFF + (t>>2)*OS  + (t&3)*8)*4);
    const uint32_t w_d  = su + (uint32_t)((WS_OFF  + (t>>1)*WTS + (t&1)*16)*4);

    // prologue: chunk 0 -> buffer 0
    cp16(o_d, obs_src); cp16(o_d + 16, obs_src + 4);
    #pragma unroll
    for (int i = 0; i < 8; ++i) cp8(w_d + i*8, w_src + i*2);
    CP_COMMIT();

    #pragma unroll 1
    for (int kc = 0; kc < NCHUNK; ++kc) {
        const int cur = kc & 1;
        if (kc < NCHUNK-1) {
            const int nxt = cur ^ 1;
            const float* os = obs_src + (kc+1)*KC;
            const float* ws = w_src   + (kc+1)*KC;
            const uint32_t od = o_d + nxt*(OBS_BUF_F*4);
            const uint32_t wd = w_d + nxt*(WS_BUF_F*4);
            cp16(od, os); cp16(od + 16, os + 4);
            #pragma unroll
            for (int i = 0; i < 8; ++i) cp8(wd + i*8, ws + i*2);
            CP_COMMIT();
            CP_WAIT1();
        } else {
            CP_WAIT0();
        }
        __syncthreads();

        const float* ob = sm + OBS_OFF + cur*OBS_BUF_F;
        const float* wb = sm + WS_OFF  + cur*WS_BUF_F;

        #pragma unroll 4
        for (int p = 0; p < KC/2; ++p) {
            ull A0 = *(const ull*)(ob + (ty     )*OS + 2*p);
            ull A1 = *(const ull*)(ob + (ty + 16)*OS + 2*p);
            ull A2 = *(const ull*)(ob + (ty + 32)*OS + 2*p);
            ull A3 = *(const ull*)(ob + (ty + 48)*OS + 2*p);
            ull B0 = *(const ull*)(wb + (tx      )*WTS + 2*p);
            ull B1 = *(const ull*)(wb + (tx + 16 )*WTS + 2*p);
            ull B2 = *(const ull*)(wb + (tx + 32 )*WTS + 2*p);
            ull B3 = *(const ull*)(wb + (tx + 48 )*WTS + 2*p);
            ull B4 = *(const ull*)(wb + (tx + 64 )*WTS + 2*p);
            ull B5 = *(const ull*)(wb + (tx + 80 )*WTS + 2*p);
            ull B6 = *(const ull*)(wb + (tx + 96 )*WTS + 2*p);
            ull B7 = *(const ull*)(wb + (tx + 112)*WTS + 2*p);
            fma2(acc[0][0], A0, B0); fma2(acc[0][1], A0, B1);
            fma2(acc[0][2], A0, B2); fma2(acc[0][3], A0, B3);
            fma2(acc[0][4], A0, B4); fma2(acc[0][5], A0, B5);
            fma2(acc[0][6], A0, B6); fma2(acc[0][7], A0, B7);
            fma2(acc[1][0], A1, B0); fma2(acc[1][1], A1, B1);
            fma2(acc[1][2], A1, B2); fma2(acc[1][3], A1, B3);
            fma2(acc[1][4], A1, B4); fma2(acc[1][5], A1, B5);
            fma2(acc[1][6], A1, B6); fma2(acc[1][7], A1, B7);
            fma2(acc[2][0], A2, B0); fma2(acc[2][1], A2, B1);
            fma2(acc[2][2], A2, B2); fma2(acc[2][3], A2, B3);
            fma2(acc[2][4], A2, B4); fma2(acc[2][5], A2, B5);
            fma2(acc[2][6], A2, B6); fma2(acc[2][7], A2, B7);
            fma2(acc[3][0], A3, B0); fma2(acc[3][1], A3, B1);
            fma2(acc[3][2], A3, B2); fma2(acc[3][3], A3, B3);
            fma2(acc[3][4], A3, B4); fma2(acc[3][5], A3, B5);
            fma2(acc[3][6], A3, B6); fma2(acc[3][7], A3, B7);
        }
        __syncthreads();
    }
}

// bias+relu -> hs staging (reuses idle weight-buffer region)
__device__ __forceinline__ void stage_relu(float* __restrict__ sm,
    const ull acc[4][8], int t, bool use_bias)
{
    const int tx = t & 15, ty = t >> 4;
    float* hs = sm + WS_OFF;
    const float* bias_s = sm + BIAS_OFF;
    #pragma unroll
    for (int i = 0; i < 4; ++i) {
        int r = ty + 16*i;
        #pragma unroll
        for (int j = 0; j < 8; ++j) {
            int c = tx + 16*j;
            float2 v = unpack2(acc[i][j]);
            float h = v.x + v.y + (use_bias ? bias_s[c] : 0.f);
            hs[r*HSS + c] = fmaxf(h, 0.f);
        }
    }
}

// ---------------------------------------------------------------------------
// Phase A: fused meta + termination nets.
// ---------------------------------------------------------------------------
__global__ void __launch_bounds__(NT, 2)
meta_term_kernel(const float* __restrict__ obs,
                 const int*   __restrict__ dones,
                 const int*   __restrict__ exec_opt,
                 const float* __restrict__ bm1,
                 const float* __restrict__ Wm_pi,
                 const float* __restrict__ Wm_v,
                 const float* __restrict__ Wt2,
                 float* __restrict__ out)
{
    extern __shared__ float sm[];
    const int t  = threadIdx.x;
    const int g0 = blockIdx.x * TB;
    float* hw     = sm + HW_OFF;
    float* bias_s = sm + BIAS_OFF;
    float* fin    = sm + FIN_OFF;
    float* hs     = sm + WS_OFF;
    int*   icnt   = (int*)(sm + MISC_OFF);

    const int row4 = t >> 2, j4 = t & 3;

    const float* obs_src = obs + (size_t)(g0 + (t>>2))*DID + (t&3)*8;

    float m0 = 0.f, m1 = 0.f, m2 = 0.f, t0 = 0.f, t1 = 0.f;

    #pragma unroll 1
    for (int net = 0; net < 2; ++net) {
        const float* wTn = g_wT + (size_t)net*HID*DID;
        #pragma unroll 1
        for (int ht = 0; ht < HID/TN; ++ht) {
            const int hbase = ht * TN;
            __syncthreads();      // hw/bias/hs free of previous readers
            if (t < TN) {
                if (net == 0) {
                    const float* wp = Wm_pi + (size_t)(hbase + t)*NOPT;
                    #pragma unroll
                    for (int o = 0; o < NOPT; ++o) hw[t*HWS + o] = wp[o];
                    hw[t*HWS + 8] = Wm_v[hbase + t];
                    bias_s[t] = bm1[hbase + t];
                } else {
                    const float* wp = Wt2 + (size_t)(hbase + t)*NOPT;
                    #pragma unroll
                    for (int o = 0; o < NOPT; ++o) hw[t*HWS + o] = wp[o];
                }
            }
            ull acc[4][8];
            #pragma unroll
            for (int i = 0; i < 4; ++i)
                #pragma unroll
                for (int j = 0; j < 8; ++j) acc[i][j] = 0ull;

            const float* w_src = wTn + (size_t)(hbase + (t>>1))*DID + (t&1)*16;
            gemm_htile(sm, obs_src, w_src, t, acc);
            stage_relu(sm, acc, t, net == 0);
            __syncthreads();

            if (net == 0) {
                #pragma unroll 8
                for (int c = 0; c < TN; ++c) {
                    float hv = hs[row4*HSS + c];
                    m0 += hv * hw[c*HWS + j4];
                    m1 += hv * hw[c*HWS + j4 + 4];
                    if (j4 == 0) m2 += hv * hw[c*HWS + 8];
                }
            } else {
                #pragma unroll 8
                for (int c = 0; c < TN; ++c) {
                    float hv = hs[row4*HSS + c];
                    t0 += hv * hw[c*HWS + j4];
                    t1 += hv * hw[c*HWS + j4 + 4];
                }
            }
        }
    }

    // finals: fin[r][0..7]=meta logits, [8]=value, [9..16]=term logits
    fin[row4*HWS + j4    ] = m0;
    fin[row4*HWS + j4 + 4] = m1;
    if (j4 == 0) fin[row4*HWS + 8] = m2;
    fin[row4*HWS + 9  + j4] = t0;
    fin[row4*HWS + 13 + j4] = t1;

    int* s_cnt  = icnt + 64;
    int* s_base = icnt + 72;
    if (t < NOPT) s_cnt[t] = 0;
    __syncthreads();

    int myno = 0, mypos = 0;
    if (t < TB) {
        int g = g0 + t;
        float lg[8];
        #pragma unroll
        for (int o = 0; o < 8; ++o) lg[o] = fin[t*HWS + o];
        float m = lg[0]; int am = 0;
        #pragma unroll
        for (int o = 1; o < 8; ++o) if (lg[o] > m) { m = lg[o]; am = o; }
        float s = 0.f;
        #pragma unroll
        for (int o = 0; o < 8; ++o) s += expf(lg[o] - m);
        float lp = -logf(s);
        float mv = fin[t*HWS + 8];
        int eo = exec_opt[g];
        float tl = fin[t*HWS + 9 + eo];
        float tp = 1.0f/(1.0f + expf(-tl));
        bool dn = (dones[g] != 0);
        bool term = dn || (tp > 0.5f);
        myno = term ? am : eo;
        out[3*B_AG + g] = (float)am;
        out[4*B_AG + g] = mv;
        out[5*B_AG + g] = lp;
        out[6*B_AG + g] = tp;
        mypos = atomicAdd(&s_cnt[myno], 1);
    }
    __syncthreads();
    if (t < NOPT) s_base[t] = atomicAdd(&g_opt_cnt[t], s_cnt[t]);
    __syncthreads();
    if (t < TB) {
        g_opt_list[myno*B_AG + s_base[myno] + mypos] = g0 + t;
    }
}

// ---------------------------------------------------------------------------
// Phase B: per-option sub-policy on compacted lists.
// ---------------------------------------------------------------------------
__global__ void __launch_bounds__(NT, 2)
subpolicy_kernel(const float* __restrict__ obs,
                 const float* __restrict__ b1,
                 const float* __restrict__ Wpi,
                 const float* __restrict__ Wv,
                 float* __restrict__ out)
{
    const int opt   = blockIdx.y;
    const int start = blockIdx.x * TB;
    const int cnt   = g_opt_cnt[opt];
    if (start >= cnt) return;
    const int nvalid = min(TB, cnt - start);

    extern __shared__ float sm[];
    const int t = threadIdx.x;
    float* hw     = sm + HW_OFF;
    float* bias_s = sm + BIAS_OFF;
    float* fin    = sm + FIN_OFF;
    float* hs     = sm + WS_OFF;
    int*   idx_s  = (int*)(sm + MISC_OFF);

    const int row4 = t >> 2, j4 = t & 3;

    if (t < TB) {
        int src = opt*B_AG + start + ((t < nvalid) ? t : 0);
        idx_s[t] = g_opt_list[src];
    }
    __syncthreads();

    const float* obs_src = obs + (size_t)idx_s[t>>2]*DID + (t&3)*8;
    const float* wTo  = g_wT + (size_t)(2 + opt)*HID*DID;
    const float* bg   = b1  + (size_t)opt*HID;
    const float* wpig = Wpi + (size_t)opt*HID*NACT;
    const float* wvg  = Wv  + (size_t)opt*HID;

    float h0 = 0.f, h1 = 0.f, h2 = 0.f, h3 = 0.f, hval = 0.f;

    #pragma unroll 1
    for (int ht = 0; ht < HID/TN; ++ht) {
        const int hbase = ht * TN;
        __syncthreads();
        if (t < TN) {
            const float* wp = wpig + (size_t)(hbase + t)*NACT;
            #pragma unroll
            for (int a = 0; a < NACT; ++a) hw[t*HWS + a] = wp[a];
            hw[t*HWS + 16] = wvg[hbase + t];
            bias_s[t] = bg[hbase + t];
        }
        ull acc[4][8];
        #pragma unroll
        for (int i = 0; i < 4; ++i)
            #pragma unroll
            for (int j = 0; j < 8; ++j) acc[i][j] = 0ull;

        const float* w_src = wTo + (size_t)(hbase + (t>>1))*DID + (t&1)*16;
        gemm_htile(sm, obs_src, w_src, t, acc);
        stage_relu(sm, acc, t, true);
        __syncthreads();

        #pragma unroll 8
        for (int c = 0; c < TN; ++c) {
            float hv = hs[row4*HSS + c];
            h0 += hv * hw[c*HWS + j4     ];
            h1 += hv * hw[c*HWS + j4 + 4 ];
            h2 += hv * hw[c*HWS + j4 + 8 ];
            h3 += hv * hw[c*HWS + j4 + 12];
            if (j4 == 0) hval += hv * hw[c*HWS + 16];
        }
    }

    fin[row4*HWS + j4     ] = h0;
    fin[row4*HWS + j4 + 4 ] = h1;
    fin[row4*HWS + j4 + 8 ] = h2;
    fin[row4*HWS + j4 + 12] = h3;
    if (j4 == 0) fin[row4*HWS + 16] = hval;
    __syncthreads();

    if (t < nvalid) {
        int g = idx_s[t];
        float lg[16];
        #pragma unroll
        for (int a = 0; a < NACT; ++a) lg[a] = fin[t*HWS + a];
        float m = lg[0]; int am = 0;
        #pragma unroll
        for (int a = 1; a < NACT; ++a) if (lg[a] > m) { m = lg[a]; am = a; }
        float s = 0.f;
        #pragma unroll
        for (int a = 0; a < NACT; ++a) s += expf(lg[a] - m);
        float lp = -logf(s);
        float val = fin[t*HWS + 16];
        out[          g] = (float)am;
        out[  B_AG +  g] = val;
        out[2*B_AG +  g] = lp;
    }
}

extern "C" void kernel_launch(void* const* d_in, const int* in_sizes, int n_in,
                              void* d_out, int out_size) {
    const float* obs      = (const float*)d_in[0];
    const int*   dones    = (const int*)  d_in[1];
    const int*   exec_opt = (const int*)  d_in[2];
    const float* Wm1      = (const float*)d_in[3];
    const float* bm1      = (const float*)d_in[4];
    const float* Wm_pi    = (const float*)d_in[5];
    const float* Wm_v     = (const float*)d_in[6];
    const float* Wt1      = (const float*)d_in[7];
    const float* Wt2      = (const float*)d_in[8];
    const float* W1       = (const float*)d_in[9];
    const float* b1       = (const float*)d_in[10];
    const float* Wpi      = (const float*)d_in[11];
    const float* Wv       = (const float*)d_in[12];
    float* out = (float*)d_out;

    cudaFuncSetAttribute(meta_term_kernel,
                         cudaFuncAttributeMaxDynamicSharedMemorySize, SMEM_BYTES);
    cudaFuncSetAttribute(subpolicy_kernel,
                         cudaFuncAttributeMaxDynamicSharedMemorySize, SMEM_BYTES);

    dim3 gT(HID/32, DID/32, 10);
    transpose_kernel<<<gT, dim3(32, 8)>>>(Wm1, Wt1, W1);
    meta_term_kernel<<<B_AG/TB, NT, SMEM_BYTES>>>(
        obs, dones, exec_opt, bm1, Wm_pi, Wm_v, Wt2, out);
    dim3 gB(B_AG/TB, NOPT);
    subpolicy_kernel<<<gB, NT, SMEM_BYTES>>>(obs, b1, Wpi, Wv, out);
}

// round 5
// speedup vs baseline: 4.2928x; 4.2928x over previous
#include <cuda_runtime.h>
#include <cuda_fp16.h>
#include <math.h>
#include <stdint.h>

#define B_AG 32768
#define DID  512
#define HID  1024
#define NOPT 8
#define NACT 16

#define MT   128           // agents per CTA
#define NTILE 64           // hidden cols per tile
#define KCH  32            // K per chunk (halves)
#define NCH  (DID/KCH)     // 16
#define NT   256

// ---- smem byte layout ----
// stage s: A_hi[128x40h] A_lo[128x40h] B_hi[64x40h] B_lo[64x40h]
#define STAGE_BYTES 30720
#define ST_OFF(s)  (1024 + (s)*STAGE_BYTES)
#define A_HI 0
#define A_LO 10240
#define B_HI 20480
#define B_LO 25600
#define HST_OFFB 1024       // fp32 h staging, aliases stage area (GEMM idle)
#define HSTS 69             // h staging stride (floats): 5r mod 32 -> conflict-free
#define HWS  20
#define HW_OFFB   62464
#define BIAS_OFFB (HW_OFFB + NTILE*HWS*4)   // 67584
#define FIN_OFFB  (BIAS_OFFB + 256)         // 67840
#define MISC_OFFB (FIN_OFFB + MT*HWS*4)     // 78080
#define SMEM_BYTES (MISC_OFFB + 768)        // 78848 -> 2 CTAs/SM fits

__device__ int    g_opt_cnt[NOPT];
__device__ int    g_opt_list[NOPT*B_AG];
__device__ __half g_obsHi[(size_t)B_AG*DID];
__device__ __half g_obsLo[(size_t)B_AG*DID];
__device__ __half g_wHiT[(size_t)10*HID*DID];   // K-major: [mat][h][k]
__device__ __half g_wLoT[(size_t)10*HID*DID];

// ---------------------------------------------------------------------------
// PTX helpers (baseline PTX only: cp.async / ldmatrix / mma.sync)
// ---------------------------------------------------------------------------
__device__ __forceinline__ void cp16(uint32_t dst, const void* src) {
    asm volatile("cp.async.cg.shared.global [%0], [%1], 16;" :: "r"(dst), "l"(src));
}
#define CP_COMMIT() asm volatile("cp.async.commit_group;")

__device__ __forceinline__ void ldm4(uint32_t a, uint32_t r[4]) {
    asm volatile("ldmatrix.sync.aligned.m8n8.x4.shared.b16 {%0,%1,%2,%3}, [%4];"
        : "=r"(r[0]), "=r"(r[1]), "=r"(r[2]), "=r"(r[3]) : "r"(a));
}
__device__ __forceinline__ void mma16816(float d[4], const uint32_t a[4],
                                         uint32_t b0, uint32_t b1) {
    asm volatile("mma.sync.aligned.m16n8k16.row.col.f32.f16.f16.f32 "
        "{%0,%1,%2,%3}, {%4,%5,%6,%7}, {%8,%9}, {%0,%1,%2,%3};"
        : "+f"(d[0]), "+f"(d[1]), "+f"(d[2]), "+f"(d[3])
        : "r"(a[0]), "r"(a[1]), "r"(a[2]), "r"(a[3]), "r"(b0), "r"(b1));
}

// ---------------------------------------------------------------------------
// Convert kernels (one-time per launch)
// ---------------------------------------------------------------------------
__global__ void __launch_bounds__(256)
convert_obs_kernel(const float* __restrict__ obs) {
    size_t i = ((size_t)blockIdx.x*256 + threadIdx.x)*8;
    float v[8]; __half hi[8], lo[8];
    #pragma unroll
    for (int k = 0; k < 8; ++k) v[k] = obs[i + k];
    #pragma unroll
    for (int k = 0; k < 8; ++k) {
        hi[k] = __float2half_rn(v[k]);
        lo[k] = __float2half_rn(v[k] - __half2float(hi[k]));
    }
    *(uint4*)&g_obsHi[i] = *(uint4*)hi;
    *(uint4*)&g_obsLo[i] = *(uint4*)lo;
    if (blockIdx.x == 0 && threadIdx.x < NOPT) g_opt_cnt[threadIdx.x] = 0;
}

__global__ void __launch_bounds__(256)
convert_w_kernel(const float* __restrict__ Wm1,
                 const float* __restrict__ Wt1,
                 const float* __restrict__ W1) {
    __shared__ float tile[32][33];
    const int m = blockIdx.z;
    const float* src = (m == 0) ? Wm1 : (m == 1) ? Wt1 : W1 + (size_t)(m-2)*DID*HID;
    const int h0 = blockIdx.x * 32;
    const int k0 = blockIdx.y * 32;
    const int tx = threadIdx.x, ty0 = threadIdx.y;
    #pragma unroll
    for (int r = 0; r < 32; r += 8)
        tile[r + ty0][tx] = src[(size_t)(k0 + r + ty0)*HID + h0 + tx];
    __syncthreads();
    __half* dHi = g_wHiT + (size_t)m*HID*DID;
    __half* dLo = g_wLoT + (size_t)m*HID*DID;
    #pragma unroll
    for (int r = 0; r < 32; r += 8) {
        float x = tile[tx][r + ty0];
        __half hi = __float2half_rn(x);
        __half lo = __float2half_rn(x - __half2float(hi));
        size_t o = (size_t)(h0 + r + ty0)*DID + k0 + tx;
        dHi[o] = hi; dLo[o] = lo;
    }
}

// ---------------------------------------------------------------------------
// Core GEMM tile: [128 x 64] over K=512, fp16 hi/lo 3-pass into f32 acc.
// Pointers are per-thread cp.async sources (k-advance handled here).
// Ends synced.
// ---------------------------------------------------------------------------
__device__ __forceinline__ void gemm_tile(uint32_t su, int t,
    const __half* aHi0, const __half* aHi1,
    const __half* aLo0, const __half* aLo1,
    const __half* bHi,  const __half* bLo,
    float acc[2][4][4])
{
    const int lane = t & 31, w = t >> 5;
    const int wm = (w & 3) * 32, wn = (w >> 2) * 32;
    const uint32_t drow = (uint32_t)((t >> 2)*80 + (t & 3)*16);

    #define FILL(s, kc) do {                                   \
        uint32_t _b = su + ST_OFF(s) + drow;                   \
        const int _ko = (kc)*KCH;                              \
        cp16(_b + A_HI,         aHi0 + _ko);                   \
        cp16(_b + A_HI + 64*80, aHi1 + _ko);                   \
        cp16(_b + A_LO,         aLo0 + _ko);                   \
        cp16(_b + A_LO + 64*80, aLo1 + _ko);                   \
        cp16(_b + B_HI,         bHi + _ko);                    \
        cp16(_b + B_LO,         bLo + _ko);                    \
        CP_COMMIT();                                           \
    } while (0)

    FILL(0, 0);

    #pragma unroll 1
    for (int kc = 0; kc < NCH; ++kc) {
        const int cur = kc & 1;
        if (kc + 1 < NCH) {
            FILL(cur ^ 1, kc + 1);
            asm volatile("cp.async.wait_group 1;");
        } else {
            asm volatile("cp.async.wait_group 0;");
        }
        __syncthreads();

        const uint32_t sb = su + ST_OFF(cur);
        #pragma unroll
        for (int ks = 0; ks < 2; ++ks) {
            const uint32_t ko = ks*32;
            const uint32_t aadr = sb + A_HI + (uint32_t)((wm + (lane & 15))*80)
                                + ko + (lane >> 4)*16;
            uint32_t ah0[4], ah1[4], al0[4], al1[4];
            ldm4(aadr,           ah0);
            ldm4(aadr + 16*80,   ah1);
            ldm4(aadr + (A_LO - A_HI),         al0);
            ldm4(aadr + (A_LO - A_HI) + 16*80, al1);

            const uint32_t badr = sb + B_HI + (uint32_t)((wn + (lane & 15))*80)
                                + ko + (lane >> 4)*16;
            uint32_t bh[4], bl[4];   // two n16 groups -> 4 n8 tiles
            uint32_t bh2[4], bl2[4];
            ldm4(badr,           bh);
            ldm4(badr + 16*80,   bh2);
            ldm4(badr + (B_LO - B_HI),         bl);
            ldm4(badr + (B_LO - B_HI) + 16*80, bl2);

            // n-tile b-frags: j0:{bh[0],bh[2]} j1:{bh[1],bh[3]} j2:{bh2[0],bh2[2]} j3:{bh2[1],bh2[3]}
            // pass 1: hi*hi
            mma16816(acc[0][0], ah0, bh[0],  bh[2]);
            mma16816(acc[0][1], ah0, bh[1],  bh[3]);
            mma16816(acc[0][2], ah0, bh2[0], bh2[2]);
            mma16816(acc[0][3], ah0, bh2[1], bh2[3]);
            mma16816(acc[1][0], ah1, bh[0],  bh[2]);
            mma16816(acc[1][1], ah1, bh[1],  bh[3]);
            mma16816(acc[1][2], ah1, bh2[0], bh2[2]);
            mma16816(acc[1][3], ah1, bh2[1], bh2[3]);
            // pass 2: hi*lo
            mma16816(acc[0][0], ah0, bl[0],  bl[2]);
            mma16816(acc[0][1], ah0, bl[1],  bl[3]);
            mma16816(acc[0][2], ah0, bl2[0], bl2[2]);
            mma16816(acc[0][3], ah0, bl2[1], bl2[3]);
            mma16816(acc[1][0], ah1, bl[0],  bl[2]);
            mma16816(acc[1][1], ah1, bl[1],  bl[3]);
            mma16816(acc[1][2], ah1, bl2[0], bl2[2]);
            mma16816(acc[1][3], ah1, bl2[1], bl2[3]);
            // pass 3: lo*hi
            mma16816(acc[0][0], al0, bh[0],  bh[2]);
            mma16816(acc[0][1], al0, bh[1],  bh[3]);
            mma16816(acc[0][2], al0, bh2[0], bh2[2]);
            mma16816(acc[0][3], al0, bh2[1], bh2[3]);
            mma16816(acc[1][0], al1, bh[0],  bh[2]);
            mma16816(acc[1][1], al1, bh[1],  bh[3]);
            mma16816(acc[1][2], al1, bh2[0], bh2[2]);
            mma16816(acc[1][3], al1, bh2[1], bh2[3]);
        }
        __syncthreads();
    }
    #undef FILL
}

// relu(acc + bias) -> h staging (aliases idle stage smem)
__device__ __forceinline__ void stage_h(float* smf, const float acc[2][4][4],
                                        int t) {
    const int lane = t & 31, w = t >> 5;
    const int wm = (w & 3) * 32, wn = (w >> 2) * 32;
    float* hst = smf + HST_OFFB/4;
    const float* bias_s = smf + BIAS_OFFB/4;
    #pragma unroll
    for (int im = 0; im < 2; ++im) {
        #pragma unroll
        for (int j = 0; j < 4; ++j) {
            #pragma unroll
            for (int e = 0; e < 4; ++e) {
                int row = wm + im*16 + (lane >> 2) + (e >> 1)*8;
                int col = wn + j*8 + 2*(lane & 3) + (e & 1);
                float h = acc[im][j][e] + bias_s[col];
                hst[row*HSTS + col] = fmaxf(h, 0.f);
            }
        }
    }
}

// ---------------------------------------------------------------------------
// Phase A: fused meta + termination nets.
// ---------------------------------------------------------------------------
__global__ void __launch_bounds__(NT, 2)
phaseA_kernel(const int*   __restrict__ dones,
              const int*   __restrict__ exec_opt,
              const float* __restrict__ bm1,
              const float* __restrict__ Wm_pi,
              const float* __restrict__ Wm_v,
              const float* __restrict__ Wt2,
              float* __restrict__ out)
{
    extern __shared__ float smf[];
    const uint32_t su = (uint32_t)__cvta_generic_to_shared(smf);
    const int t = threadIdx.x;
    const int g0 = blockIdx.x * MT;

    float* hw     = smf + HW_OFFB/4;
    float* bias_s = smf + BIAS_OFFB/4;
    float* fin    = smf + FIN_OFFB/4;
    float* hst    = smf + HST_OFFB/4;
    int*   icnt   = (int*)(smf + MISC_OFFB/4);

    // per-thread cp.async sources for obs rows
    const size_t arow0 = (size_t)(g0 + (t >> 2))*DID + (t & 3)*8;
    const size_t arow1 = arow0 + (size_t)64*DID;
    const __half* aHi0 = g_obsHi + arow0;
    const __half* aHi1 = g_obsHi + arow1;
    const __half* aLo0 = g_obsLo + arow0;
    const __half* aLo1 = g_obsLo + arow1;

    float accM[9], accT[8];
    #pragma unroll
    for (int k = 0; k < 9; ++k) accM[k] = 0.f;
    #pragma unroll
    for (int k = 0; k < 8; ++k) accT[k] = 0.f;

    const int r = t & 127, cbase = (t >> 7)*32;

    #pragma unroll 1
    for (int net = 0; net < 2; ++net) {
        #pragma unroll 1
        for (int ht = 0; ht < HID/NTILE; ++ht) {
            const int hbase = ht * NTILE;
            if (t < NTILE) {
                if (net == 0) {
                    const float* wp = Wm_pi + (size_t)(hbase + t)*NOPT;
                    #pragma unroll
                    for (int o = 0; o < NOPT; ++o) hw[t*HWS + o] = wp[o];
                    hw[t*HWS + 8] = Wm_v[hbase + t];
                    bias_s[t] = bm1[hbase + t];
                } else {
                    const float* wp = Wt2 + (size_t)(hbase + t)*NOPT;
                    #pragma unroll
                    for (int o = 0; o < NOPT; ++o) hw[t*HWS + o] = wp[o];
                    bias_s[t] = 0.f;
                }
            }
            const size_t brow = ((size_t)net*HID + hbase + (t >> 2))*DID + (t & 3)*8;
            const __half* bHi = g_wHiT + brow;
            const __half* bLo = g_wLoT + brow;

            float acc[2][4][4];
            #pragma unroll
            for (int i = 0; i < 2; ++i)
                #pragma unroll
                for (int j = 0; j < 4; ++j)
                    #pragma unroll
                    for (int e = 0; e < 4; ++e) acc[i][j][e] = 0.f;

            gemm_tile(su, t, aHi0, aHi1, aLo0, aLo1, bHi, bLo, acc);
            stage_h(smf, acc, t);
            __syncthreads();

            // head contraction: thread owns row r, col half cbase..cbase+31
            if (net == 0) {
                #pragma unroll 4
                for (int c = 0; c < 32; ++c) {
                    float h = hst[r*HSTS + cbase + c];
                    const float* hwc = hw + (cbase + c)*HWS;
                    float4 w0 = *(const float4*)(hwc);
                    float4 w1 = *(const float4*)(hwc + 4);
                    accM[0] += h*w0.x; accM[1] += h*w0.y;
                    accM[2] += h*w0.z; accM[3] += h*w0.w;
                    accM[4] += h*w1.x; accM[5] += h*w1.y;
                    accM[6] += h*w1.z; accM[7] += h*w1.w;
                    accM[8] += h*hwc[8];
                }
            } else {
                #pragma unroll 4
                for (int c = 0; c < 32; ++c) {
                    float h = hst[r*HSTS + cbase + c];
                    const float* hwc = hw + (cbase + c)*HWS;
                    float4 w0 = *(const float4*)(hwc);
                    float4 w1 = *(const float4*)(hwc + 4);
                    accT[0] += h*w0.x; accT[1] += h*w0.y;
                    accT[2] += h*w0.z; accT[3] += h*w0.w;
                    accT[4] += h*w1.x; accT[5] += h*w1.y;
                    accT[6] += h*w1.z; accT[7] += h*w1.w;
                }
            }
            __syncthreads();   // hst/hw free before next tile
        }
    }

    // cross-half reduction
    if (t >= 128) {
        #pragma unroll
        for (int k = 0; k < 9; ++k) fin[r*HWS + k] = accM[k];
        #pragma unroll
        for (int k = 0; k < 8; ++k) fin[r*HWS + 9 + k] = accT[k];
    }
    int* s_cnt  = icnt + 160;
    int* s_base = icnt + 168;
    if (t < NOPT) s_cnt[t] = 0;
    __syncthreads();

    int myno = 0, mypos = 0;
    if (t < MT) {
        const int g = g0 + t;
        float lg[8];
        #pragma unroll
        for (int o = 0; o < 8; ++o) lg[o] = accM[o] + fin[t*HWS + o];
        float mv = accM[8] + fin[t*HWS + 8];
        float m = lg[0]; int am = 0;
        #pragma unroll
        for (int o = 1; o < 8; ++o) if (lg[o] > m) { m = lg[o]; am = o; }
        float s = 0.f;
        #pragma unroll
        for (int o = 0; o < 8; ++o) s += expf(lg[o] - m);
        float lp = -logf(s);
        int eo = exec_opt[g];
        float tl = accT[eo] + fin[t*HWS + 9 + eo];
        float tp = 1.0f/(1.0f + expf(-tl));
        bool dn = (dones[g] != 0);
        bool term = dn || (tp > 0.5f);
        myno = term ? am : eo;
        out[3*B_AG + g] = (float)am;
        out[4*B_AG + g] = mv;
        out[5*B_AG + g] = lp;
        out[6*B_AG + g] = tp;
        mypos = atomicAdd(&s_cnt[myno], 1);
    }
    __syncthreads();
    if (t < NOPT) s_base[t] = atomicAdd(&g_opt_cnt[t], s_cnt[t]);
    __syncthreads();
    if (t < MT) g_opt_list[myno*B_AG + s_base[myno] + mypos] = g0 + t;
}

// ---------------------------------------------------------------------------
// Phase B: per-option sub-policy on compacted lists.
// ---------------------------------------------------------------------------
__global__ void __launch_bounds__(NT, 2)
phaseB_kernel(const float* __restrict__ b1,
              const float* __restrict__ Wpi,
              const float* __restrict__ Wv,
              float* __restrict__ out)
{
    const int opt   = blockIdx.y;
    const int start = blockIdx.x * MT;
    const int cnt   = g_opt_cnt[opt];
    if (start >= cnt) return;
    const int nvalid = min(MT, cnt - start);

    extern __shared__ float smf[];
    const uint32_t su = (uint32_t)__cvta_generic_to_shared(smf);
    const int t = threadIdx.x;

    float* hw     = smf + HW_OFFB/4;
    float* bias_s = smf + BIAS_OFFB/4;
    float* fin    = smf + FIN_OFFB/4;
    float* hst    = smf + HST_OFFB/4;
    int*   idx_s  = (int*)(smf + MISC_OFFB/4);

    if (t < MT) {
        int src = opt*B_AG + start + ((t < nvalid) ? t : 0);
        idx_s[t] = g_opt_list[src];
    }
    __syncthreads();

    const size_t arow0 = (size_t)idx_s[t >> 2]*DID + (t & 3)*8;
    const size_t arow1 = (size_t)idx_s[64 + (t >> 2)]*DID + (t & 3)*8;
    const __half* aHi0 = g_obsHi + arow0;
    const __half* aHi1 = g_obsHi + arow1;
    const __half* aLo0 = g_obsLo + arow0;
    const __half* aLo1 = g_obsLo + arow1;

    const float* bg   = b1  + (size_t)opt*HID;
    const float* wpig = Wpi + (size_t)opt*HID*NACT;
    const float* wvg  = Wv  + (size_t)opt*HID;

    float accB[17];
    #pragma unroll
    for (int k = 0; k < 17; ++k) accB[k] = 0.f;

    const int r = t & 127, cbase = (t >> 7)*32;

    #pragma unroll 1
    for (int ht = 0; ht < HID/NTILE; ++ht) {
        const int hbase = ht * NTILE;
        if (t < NTILE) {
            const float* wp = wpig + (size_t)(hbase + t)*NACT;
            #pragma unroll
            for (int a = 0; a < NACT; ++a) hw[t*HWS + a] = wp[a];
            hw[t*HWS + 16] = wvg[hbase + t];
            bias_s[t] = bg[hbase + t];
        }
        const size_t brow = ((size_t)(2 + opt)*HID + hbase + (t >> 2))*DID + (t & 3)*8;
        const __half* bHi = g_wHiT + brow;
        const __half* bLo = g_wLoT + brow;

        float acc[2][4][4];
        #pragma unroll
        for (int i = 0; i < 2; ++i)
            #pragma unroll
            for (int j = 0; j < 4; ++j)
                #pragma unroll
                for (int e = 0; e < 4; ++e) acc[i][j][e] = 0.f;

        gemm_tile(su, t, aHi0, aHi1, aLo0, aLo1, bHi, bLo, acc);
        stage_h(smf, acc, t);
        __syncthreads();

        #pragma unroll 4
        for (int c = 0; c < 32; ++c) {
            float h = hst[r*HSTS + cbase + c];
            const float* hwc = hw + (cbase + c)*HWS;
            float4 w0 = *(const float4*)(hwc);
            float4 w1 = *(const float4*)(hwc + 4);
            float4 w2 = *(const float4*)(hwc + 8);
            float4 w3 = *(const float4*)(hwc + 12);
            accB[0]  += h*w0.x; accB[1]  += h*w0.y;
            accB[2]  += h*w0.z; accB[3]  += h*w0.w;
            accB[4]  += h*w1.x; accB[5]  += h*w1.y;
            accB[6]  += h*w1.z; accB[7]  += h*w1.w;
            accB[8]  += h*w2.x; accB[9]  += h*w2.y;
            accB[10] += h*w2.z; accB[11] += h*w2.w;
            accB[12] += h*w3.x; accB[13] += h*w3.y;
            accB[14] += h*w3.z; accB[15] += h*w3.w;
            accB[16] += h*hwc[16];
        }
        __syncthreads();
    }

    if (t >= 128) {
        #pragma unroll
        for (int k = 0; k < 17; ++k) fin[r*HWS + k] = accB[k];
    }
    __syncthreads();

    if (t < MT && t < nvalid) {
        const int g = idx_s[t];
        float lg[16];
        #pragma unroll
        for (int a = 0; a < NACT; ++a) lg[a] = accB[a] + fin[t*HWS + a];
        float val = accB[16] + fin[t*HWS + 16];
        float m = lg[0]; int am = 0;
        #pragma unroll
        for (int a = 1; a < NACT; ++a) if (lg[a] > m) { m = lg[a]; am = a; }
        float s = 0.f;
        #pragma unroll
        for (int a = 0; a < NACT; ++a) s += expf(lg[a] - m);
        float lp = -logf(s);
        out[          g] = (float)am;
        out[  B_AG +  g] = val;
        out[2*B_AG +  g] = lp;
    }
}

extern "C" void kernel_launch(void* const* d_in, const int* in_sizes, int n_in,
                              void* d_out, int out_size) {
    const float* obs      = (const float*)d_in[0];
    const int*   dones    = (const int*)  d_in[1];
    const int*   exec_opt = (const int*)  d_in[2];
    const float* Wm1      = (const float*)d_in[3];
    const float* bm1      = (const float*)d_in[4];
    const float* Wm_pi    = (const float*)d_in[5];
    const float* Wm_v     = (const float*)d_in[6];
    const float* Wt1      = (const float*)d_in[7];
    const float* Wt2      = (const float*)d_in[8];
    const float* W1       = (const float*)d_in[9];
    const float* b1       = (const float*)d_in[10];
    const float* Wpi      = (const float*)d_in[11];
    const float* Wv       = (const float*)d_in[12];
    float* out = (float*)d_out;

    cudaFuncSetAttribute(phaseA_kernel,
                         cudaFuncAttributeMaxDynamicSharedMemorySize, SMEM_BYTES);
    cudaFuncSetAttribute(phaseB_kernel,
                         cudaFuncAttributeMaxDynamicSharedMemorySize, SMEM_BYTES);

    convert_obs_kernel<<<(B_AG*DID)/(256*8), 256>>>(obs);
    dim3 gW(HID/32, DID/32, 10);
    convert_w_kernel<<<gW, dim3(32, 8)>>>(Wm1, Wt1, W1);
    phaseA_kernel<<<B_AG/MT, NT, SMEM_BYTES>>>(
        dones, exec_opt, bm1, Wm_pi, Wm_v, Wt2, out);
    dim3 gB(B_AG/MT, NOPT);
    phaseB_kernel<<<gB, NT, SMEM_BYTES>>>(b1, Wpi, Wv, out);
}

// round 7
// speedup vs baseline: 4.3559x; 1.0147x over previous
#include <cuda_runtime.h>
#include <cuda_fp16.h>
#include <math.h>
#include <stdint.h>

#define B_AG 32768
#define DID  512
#define HID  1024
#define NOPT 8
#define NACT 16

#define MT    64           // agents per CTA
#define NTILE 128          // hidden cols per tile
#define KCH   32           // K per chunk (halves)
#define NCH   (DID/KCH)    // 16
#define NT    128

// ---- smem byte layout ----
// stage s: A_hi[64x80B] A_lo[64x80B] B_hi[128x80B] B_lo[128x80B]
#define A_HI 0
#define A_LO 5120
#define B_HI 10240
#define B_LO 20480
#define STAGE_BYTES 30720
#define ST_OFF(s)  (1024 + (s)*STAGE_BYTES)
// h staging + final staging alias the (idle-at-that-point) stage area
#define HST_OFFB 1024
#define HSTS 133            // floats; 133 mod 32 = 5 -> conflict-free col reads
#define FIN_OFFB 35072      // 1024 + 64*133*4
#define FINS 20
#define HWS  20
#define HW_OFFB   62464     // 1024 + 2*30720
#define BIAS_OFFB 72704     // HW + 128*20*4
#define MISC_OFFB 73216
#define SMEM_BYTES 73984    // x3 CTAs = 221952 < 228KB

__device__ int    g_opt_cnt[NOPT];
__device__ int    g_opt_list[NOPT*B_AG];
__device__ __half g_obsHi[(size_t)B_AG*DID];
__device__ __half g_obsLo[(size_t)B_AG*DID];
__device__ __half g_wHiT[(size_t)10*HID*DID];   // K-major: [mat][h][k]
__device__ __half g_wLoT[(size_t)10*HID*DID];

// ---------------------------------------------------------------------------
// PTX helpers (baseline PTX only: cp.async / ldmatrix / mma.sync)
// ---------------------------------------------------------------------------
__device__ __forceinline__ void cp16(uint32_t dst, const void* src) {
    asm volatile("cp.async.cg.shared.global [%0], [%1], 16;" :: "r"(dst), "l"(src));
}
#define CP_COMMIT() asm volatile("cp.async.commit_group;")

__device__ __forceinline__ void ldm4(uint32_t a, uint32_t r[4]) {
    asm volatile("ldmatrix.sync.aligned.m8n8.x4.shared.b16 {%0,%1,%2,%3}, [%4];"
        : "=r"(r[0]), "=r"(r[1]), "=r"(r[2]), "=r"(r[3]) : "r"(a));
}
__device__ __forceinline__ void mma16816(float d[4], const uint32_t a[4],
                                         uint32_t b0, uint32_t b1) {
    asm volatile("mma.sync.aligned.m16n8k16.row.col.f32.f16.f16.f32 "
        "{%0,%1,%2,%3}, {%4,%5,%6,%7}, {%8,%9}, {%0,%1,%2,%3};"
        : "+f"(d[0]), "+f"(d[1]), "+f"(d[2]), "+f"(d[3])
        : "r"(a[0]), "r"(a[1]), "r"(a[2]), "r"(a[3]), "r"(b0), "r"(b1));
}

// ---------------------------------------------------------------------------
// Convert kernels (one-time per launch)
// ---------------------------------------------------------------------------
__global__ void __launch_bounds__(256)
convert_obs_kernel(const float* __restrict__ obs) {
    size_t i = ((size_t)blockIdx.x*256 + threadIdx.x)*8;
    float v[8]; __half hi[8], lo[8];
    #pragma unroll
    for (int k = 0; k < 8; ++k) v[k] = obs[i + k];
    #pragma unroll
    for (int k = 0; k < 8; ++k) {
        hi[k] = __float2half_rn(v[k]);
        lo[k] = __float2half_rn(v[k] - __half2float(hi[k]));
    }
    *(uint4*)&g_obsHi[i] = *(uint4*)hi;
    *(uint4*)&g_obsLo[i] = *(uint4*)lo;
    if (blockIdx.x == 0 && threadIdx.x < NOPT) g_opt_cnt[threadIdx.x] = 0;
}

__global__ void __launch_bounds__(256)
convert_w_kernel(const float* __restrict__ Wm1,
                 const float* __restrict__ Wt1,
                 const float* __restrict__ W1) {
    __shared__ float tile[32][33];
    const int m = blockIdx.z;
    const float* src = (m == 0) ? Wm1 : (m == 1) ? Wt1 : W1 + (size_t)(m-2)*DID*HID;
    const int h0 = blockIdx.x * 32;
    const int k0 = blockIdx.y * 32;
    const int tx = threadIdx.x, ty0 = threadIdx.y;
    #pragma unroll
    for (int r = 0; r < 32; r += 8)
        tile[r + ty0][tx] = src[(size_t)(k0 + r + ty0)*HID + h0 + tx];
    __syncthreads();
    __half* dHi = g_wHiT + (size_t)m*HID*DID;
    __half* dLo = g_wLoT + (size_t)m*HID*DID;
    #pragma unroll
    for (int r = 0; r < 32; r += 8) {
        float x = tile[tx][r + ty0];
        __half hi = __float2half_rn(x);
        __half lo = __float2half_rn(x - __half2float(hi));
        size_t o = (size_t)(h0 + r + ty0)*DID + k0 + tx;
        dHi[o] = hi; dLo[o] = lo;
    }
}

// ---------------------------------------------------------------------------
// Core GEMM tile: [64 x 128] over K=512, fp16 hi/lo 3-pass into f32 acc.
// 4 warps: wm=(w&1)*32, wn=(w>>1)*64; warp tile 32x64. Ends synced.
// ---------------------------------------------------------------------------
__device__ __forceinline__ void gemm_tile(uint32_t su, int t,
    const __half* aHi0, const __half* aHi1,
    const __half* aLo0, const __half* aLo1,
    const __half* bHi,  const __half* bLo,
    float acc[2][8][4])
{
    const int lane = t & 31, w = t >> 5;
    const int wm = (w & 1) * 32, wn = (w >> 1) * 64;
    const uint32_t drow = (uint32_t)((t >> 2)*80 + (t & 3)*16);

    #define FILL(s, kc) do {                                    \
        uint32_t _b = su + ST_OFF(s) + drow;                    \
        const int _ko = (kc)*KCH;                               \
        cp16(_b + A_HI,        aHi0 + _ko);                     \
        cp16(_b + A_HI + 2560, aHi1 + _ko);                     \
        cp16(_b + A_LO,        aLo0 + _ko);                     \
        cp16(_b + A_LO + 2560, aLo1 + _ko);                     \
        _Pragma("unroll")                                       \
        for (int _i = 0; _i < 4; ++_i) {                        \
            cp16(_b + B_HI + _i*2560, bHi + _i*32*DID + _ko);   \
            cp16(_b + B_LO + _i*2560, bLo + _i*32*DID + _ko);   \
        }                                                       \
        CP_COMMIT();                                            \
    } while (0)

    FILL(0, 0);

    #pragma unroll 1
    for (int kc = 0; kc < NCH; ++kc) {
        const int cur = kc & 1;
        if (kc + 1 < NCH) {
            FILL(cur ^ 1, kc + 1);
            asm volatile("cp.async.wait_group 1;");
        } else {
            asm volatile("cp.async.wait_group 0;");
        }
        __syncthreads();

        const uint32_t sb = su + ST_OFF(cur);
        #pragma unroll
        for (int ks = 0; ks < 2; ++ks) {
            const uint32_t ko = ks*32 + (lane >> 4)*16;
            const uint32_t aadr = sb + A_HI + (uint32_t)((wm + (lane & 15))*80) + ko;
            uint32_t ah0[4], ah1[4], al0[4], al1[4];
            ldm4(aadr,          ah0);
            ldm4(aadr + 16*80,  ah1);
            ldm4(aadr + 5120,         al0);
            ldm4(aadr + 5120 + 16*80, al1);

            uint32_t bh[4][4], bl[4][4];
            #pragma unroll
            for (int j = 0; j < 4; ++j) {
                const uint32_t badr = sb + B_HI
                    + (uint32_t)((wn + j*16 + (lane & 15))*80) + ko;
                ldm4(badr,         bh[j]);
                ldm4(badr + 10240, bl[j]);
            }

            // pass 1: hi*hi
            #pragma unroll
            for (int j = 0; j < 4; ++j) {
                mma16816(acc[0][2*j  ], ah0, bh[j][0], bh[j][2]);
                mma16816(acc[0][2*j+1], ah0, bh[j][1], bh[j][3]);
                mma16816(acc[1][2*j  ], ah1, bh[j][0], bh[j][2]);
                mma16816(acc[1][2*j+1], ah1, bh[j][1], bh[j][3]);
            }
            // pass 2: hi*lo
            #pragma unroll
            for (int j = 0; j < 4; ++j) {
                mma16816(acc[0][2*j  ], ah0, bl[j][0], bl[j][2]);
                mma16816(acc[0][2*j+1], ah0, bl[j][1], bl[j][3]);
                mma16816(acc[1][2*j  ], ah1, bl[j][0], bl[j][2]);
                mma16816(acc[1][2*j+1], ah1, bl[j][1], bl[j][3]);
            }
            // pass 3: lo*hi
            #pragma unroll
            for (int j = 0; j < 4; ++j) {
                mma16816(acc[0][2*j  ], al0, bh[j][0], bh[j][2]);
                mma16816(acc[0][2*j+1], al0, bh[j][1], bh[j][3]);
                mma16816(acc[1][2*j  ], al1, bh[j][0], bh[j][2]);
                mma16816(acc[1][2*j+1], al1, bh[j][1], bh[j][3]);
            }
        }
        __syncthreads();
    }
    #undef FILL
}

// relu(acc + bias) -> h staging (aliases idle stage smem)
// NOTE: scalar stores only — HSTS is odd, float2 stores would be misaligned.
__device__ __forceinline__ void stage_h(float* smf, const float acc[2][8][4],
                                        int t) {
    const int lane = t & 31, w = t >> 5;
    const int wm = (w & 1) * 32, wn = (w >> 1) * 64;
    float* hst = smf + HST_OFFB/4;
    const float* bias_s = smf + BIAS_OFFB/4;
    #pragma unroll
    for (int im = 0; im < 2; ++im) {
        #pragma unroll
        for (int j = 0; j < 8; ++j) {
            #pragma unroll
            for (int e = 0; e < 4; ++e) {
                int row = wm + im*16 + (lane >> 2) + (e >> 1)*8;
                int col = wn + j*8 + 2*(lane & 3) + (e & 1);
                float h = acc[im][j][e] + bias_s[col];
                hst[row*HSTS + col] = fmaxf(h, 0.f);
            }
        }
    }
}

// ---------------------------------------------------------------------------
// Phase A: fused meta + termination nets.
// ---------------------------------------------------------------------------
__global__ void __launch_bounds__(NT, 3)
phaseA_kernel(const int*   __restrict__ dones,
              const int*   __restrict__ exec_opt,
              const float* __restrict__ bm1,
              const float* __restrict__ Wm_pi,
              const float* __restrict__ Wm_v,
              const float* __restrict__ Wt2,
              float* __restrict__ out)
{
    extern __shared__ float smf[];
    const uint32_t su = (uint32_t)__cvta_generic_to_shared(smf);
    const int t = threadIdx.x;
    const int g0 = blockIdx.x * MT;

    float* hw     = smf + HW_OFFB/4;
    float* bias_s = smf + BIAS_OFFB/4;
    float* fin    = smf + FIN_OFFB/4;
    float* hst    = smf + HST_OFFB/4;
    int*   icnt   = (int*)(smf + MISC_OFFB/4);

    const size_t arow = (size_t)(g0 + (t >> 2))*DID + (t & 3)*8;
    const __half* aHi0 = g_obsHi + arow;
    const __half* aHi1 = aHi0 + (size_t)32*DID;
    const __half* aLo0 = g_obsLo + arow;
    const __half* aLo1 = aLo0 + (size_t)32*DID;

    float accM[9], accT[8];
    #pragma unroll
    for (int k = 0; k < 9; ++k) accM[k] = 0.f;
    #pragma unroll
    for (int k = 0; k < 8; ++k) accT[k] = 0.f;

    const int r = t & 63, cbase = (t >> 6)*64;

    #pragma unroll 1
    for (int net = 0; net < 2; ++net) {
        #pragma unroll 1
        for (int ht = 0; ht < HID/NTILE; ++ht) {
            const int hbase = ht * NTILE;
            if (net == 0) {
                const float* wp = Wm_pi + (size_t)(hbase + t)*NOPT;
                #pragma unroll
                for (int o = 0; o < NOPT; ++o) hw[t*HWS + o] = wp[o];
                hw[t*HWS + 8] = Wm_v[hbase + t];
                bias_s[t] = bm1[hbase + t];
            } else {
                const float* wp = Wt2 + (size_t)(hbase + t)*NOPT;
                #pragma unroll
                for (int o = 0; o < NOPT; ++o) hw[t*HWS + o] = wp[o];
                bias_s[t] = 0.f;
            }
            const size_t brow = ((size_t)net*HID + hbase + (t >> 2))*DID + (t & 3)*8;
            const __half* bHi = g_wHiT + brow;
            const __half* bLo = g_wLoT + brow;

            float acc[2][8][4];
            #pragma unroll
            for (int i = 0; i < 2; ++i)
                #pragma unroll
                for (int j = 0; j < 8; ++j)
                    #pragma unroll
                    for (int e = 0; e < 4; ++e) acc[i][j][e] = 0.f;

            gemm_tile(su, t, aHi0, aHi1, aLo0, aLo1, bHi, bLo, acc);
            stage_h(smf, acc, t);
            __syncthreads();

            if (net == 0) {
                #pragma unroll 4
                for (int c = 0; c < 64; ++c) {
                    float h = hst[r*HSTS + cbase + c];
                    const float* hwc = hw + (cbase + c)*HWS;
                    float4 w0 = *(const float4*)(hwc);
                    float4 w1 = *(const float4*)(hwc + 4);
                    accM[0] += h*w0.x; accM[1] += h*w0.y;
                    accM[2] += h*w0.z; accM[3] += h*w0.w;
                    accM[4] += h*w1.x; accM[5] += h*w1.y;
                    accM[6] += h*w1.z; accM[7] += h*w1.w;
                    accM[8] += h*hwc[8];
                }
            } else {
                #pragma unroll 4
                for (int c = 0; c < 64; ++c) {
                    float h = hst[r*HSTS + cbase + c];
                    const float* hwc = hw + (cbase + c)*HWS;
                    float4 w0 = *(const float4*)(hwc);
                    float4 w1 = *(const float4*)(hwc + 4);
                    accT[0] += h*w0.x; accT[1] += h*w0.y;
                    accT[2] += h*w0.z; accT[3] += h*w0.w;
                    accT[4] += h*w1.x; accT[5] += h*w1.y;
                    accT[6] += h*w1.z; accT[7] += h*w1.w;
                }
            }
            __syncthreads();   // hst/hw/bias free before next tile
        }
    }

    // cross-col-half reduction via FIN
    if (t >= 64) {
        #pragma unroll
        for (int k = 0; k < 9; ++k) fin[r*FINS + k] = accM[k];
        #pragma unroll
        for (int k = 0; k < 8; ++k) fin[r*FINS + 9 + k] = accT[k];
    }
    int* s_cnt  = icnt + 32;
    int* s_base = icnt + 40;
    if (t < NOPT) s_cnt[t] = 0;
    __syncthreads();

    int myno = 0, mypos = 0;
    if (t < MT) {
        const int g = g0 + t;
        float lg[8];
        #pragma unroll
        for (int o = 0; o < 8; ++o) lg[o] = accM[o] + fin[t*FINS + o];
        float mv = accM[8] + fin[t*FINS + 8];
        float m = lg[0]; int am = 0;
        #pragma unroll
        for (int o = 1; o < 8; ++o) if (lg[o] > m) { m = lg[o]; am = o; }
        float s = 0.f;
        #pragma unroll
        for (int o = 0; o < 8; ++o) s += expf(lg[o] - m);
        float lp = -logf(s);
        int eo = exec_opt[g];
        float tl = accT[eo] + fin[t*FINS + 9 + eo];
        float tp = 1.0f/(1.0f + expf(-tl));
        bool dn = (dones[g] != 0);
        bool term = dn || (tp > 0.5f);
        myno = term ? am : eo;
        out[3*B_AG + g] = (float)am;
        out[4*B_AG + g] = mv;
        out[5*B_AG + g] = lp;
        out[6*B_AG + g] = tp;
        mypos = atomicAdd(&s_cnt[myno], 1);
    }
    __syncthreads();
    if (t < NOPT) s_base[t] = atomicAdd(&g_opt_cnt[t], s_cnt[t]);
    __syncthreads();
    if (t < MT) g_opt_list[myno*B_AG + s_base[myno] + mypos] = g0 + t;
}

// ---------------------------------------------------------------------------
// Phase B: per-option sub-policy on compacted lists.
// ---------------------------------------------------------------------------
__global__ void __launch_bounds__(NT, 3)
phaseB_kernel(const float* __restrict__ b1,
              const float* __restrict__ Wpi,
              const float* __restrict__ Wv,
              float* __restrict__ out)
{
    const int opt   = blockIdx.y;
    const int start = blockIdx.x * MT;
    const int cnt   = g_opt_cnt[opt];
    if (start >= cnt) return;
    const int nvalid = min(MT, cnt - start);

    extern __shared__ float smf[];
    const uint32_t su = (uint32_t)__cvta_generic_to_shared(smf);
    const int t = threadIdx.x;

    float* hw     = smf + HW_OFFB/4;
    float* bias_s = smf + BIAS_OFFB/4;
    float* fin    = smf + FIN_OFFB/4;
    float* hst    = smf + HST_OFFB/4;
    int*   idx_s  = (int*)(smf + MISC_OFFB/4);

    if (t < MT) {
        int src = opt*B_AG + start + ((t < nvalid) ? t : 0);
        idx_s[t] = g_opt_list[src];
    }
    __syncthreads();

    const size_t arow0 = (size_t)idx_s[t >> 2]*DID + (t & 3)*8;
    const size_t arow1 = (size_t)idx_s[(t >> 2) + 32]*DID + (t & 3)*8;
    const __half* aHi0 = g_obsHi + arow0;
    const __half* aHi1 = g_obsHi + arow1;
    const __half* aLo0 = g_obsLo + arow0;
    const __half* aLo1 = g_obsLo + arow1;

    const float* bg   = b1  + (size_t)opt*HID;
    const float* wpig = Wpi + (size_t)opt*HID*NACT;
    const float* wvg  = Wv  + (size_t)opt*HID;

    float accB[17];
    #pragma unroll
    for (int k = 0; k < 17; ++k) accB[k] = 0.f;

    const int r = t & 63, cbase = (t >> 6)*64;

    #pragma unroll 1
    for (int ht = 0; ht < HID/NTILE; ++ht) {
        const int hbase = ht * NTILE;
        {
            const float* wp = wpig + (size_t)(hbase + t)*NACT;
            #pragma unroll
            for (int a = 0; a < NACT; ++a) hw[t*HWS + a] = wp[a];
            hw[t*HWS + 16] = wvg[hbase + t];
            bias_s[t] = bg[hbase + t];
        }
        const size_t brow = ((size_t)(2 + opt)*HID + hbase + (t >> 2))*DID + (t & 3)*8;
        const __half* bHi = g_wHiT + brow;
        const __half* bLo = g_wLoT + brow;

        float acc[2][8][4];
        #pragma unroll
        for (int i = 0; i < 2; ++i)
            #pragma unroll
            for (int j = 0; j < 8; ++j)
                #pragma unroll
                for (int e = 0; e < 4; ++e) acc[i][j][e] = 0.f;

        gemm_tile(su, t, aHi0, aHi1, aLo0, aLo1, bHi, bLo, acc);
        stage_h(smf, acc, t);
        __syncthreads();

        #pragma unroll 2
        for (int c = 0; c < 64; ++c) {
            float h = hst[r*HSTS + cbase + c];
            const float* hwc = hw + (cbase + c)*HWS;
            float4 w0 = *(const float4*)(hwc);
            float4 w1 = *(const float4*)(hwc + 4);
            float4 w2 = *(const float4*)(hwc + 8);
            float4 w3 = *(const float4*)(hwc + 12);
            accB[0]  += h*w0.x; accB[1]  += h*w0.y;
            accB[2]  += h*w0.z; accB[3]  += h*w0.w;
            accB[4]  += h*w1.x; accB[5]  += h*w1.y;
            accB[6]  += h*w1.z; accB[7]  += h*w1.w;
            accB[8]  += h*w2.x; accB[9]  += h*w2.y;
            accB[10] += h*w2.z; accB[11] += h*w2.w;
            accB[12] += h*w3.x; accB[13] += h*w3.y;
            accB[14] += h*w3.z; accB[15] += h*w3.w;
            accB[16] += h*hwc[16];
        }
        __syncthreads();
    }

    if (t >= 64) {
        #pragma unroll
        for (int k = 0; k < 17; ++k) fin[r*FINS + k] = accB[k];
    }
    __syncthreads();

    if (t < MT && t < nvalid) {
        const int g = idx_s[t];
        float lg[16];
        #pragma unroll
        for (int a = 0; a < NACT; ++a) lg[a] = accB[a] + fin[t*FINS + a];
        float val = accB[16] + fin[t*FINS + 16];
        float m = lg[0]; int am = 0;
        #pragma unroll
        for (int a = 1; a < NACT; ++a) if (lg[a] > m) { m = lg[a]; am = a; }
        float s = 0.f;
        #pragma unroll
        for (int a = 0; a < NACT; ++a) s += expf(lg[a] - m);
        float lp = -logf(s);
        out[          g] = (float)am;
        out[  B_AG +  g] = val;
        out[2*B_AG +  g] = lp;
    }
}

extern "C" void kernel_launch(void* const* d_in, const int* in_sizes, int n_in,
                              void* d_out, int out_size) {
    const float* obs      = (const float*)d_in[0];
    const int*   dones    = (const int*)  d_in[1];
    const int*   exec_opt = (const int*)  d_in[2];
    const float* Wm1      = (const float*)d_in[3];
    const float* bm1      = (const float*)d_in[4];
    const float* Wm_pi    = (const float*)d_in[5];
    const float* Wm_v     = (const float*)d_in[6];
    const float* Wt1      = (const float*)d_in[7];
    const float* Wt2      = (const float*)d_in[8];
    const float* W1       = (const float*)d_in[9];
    const float* b1       = (const float*)d_in[10];
    const float* Wpi      = (const float*)d_in[11];
    const float* Wv       = (const float*)d_in[12];
    float* out = (float*)d_out;

    cudaFuncSetAttribute(phaseA_kernel,
                         cudaFuncAttributeMaxDynamicSharedMemorySize, SMEM_BYTES);
    cudaFuncSetAttribute(phaseB_kernel,
                         cudaFuncAttributeMaxDynamicSharedMemorySize, SMEM_BYTES);

    convert_obs_kernel<<<(B_AG*DID)/(256*8), 256>>>(obs);
    dim3 gW(HID/32, DID/32, 10);
    convert_w_kernel<<<gW, dim3(32, 8)>>>(Wm1, Wt1, W1);
    phaseA_kernel<<<B_AG/MT, NT, SMEM_BYTES>>>(
        dones, exec_opt, bm1, Wm_pi, Wm_v, Wt2, out);
    dim3 gB(B_AG/MT, NOPT);
    phaseB_kernel<<<gB, NT, SMEM_BYTES>>>(b1, Wpi, Wv, out);
}